// round 14
// baseline (speedup 1.0000x reference)
#include <cuda_runtime.h>
#include <cuda_fp16.h>
#include <cstdint>
#include <cmath>

#define Bb 1024
#define Ll 128
#define Ww 512
#define Ss 8
#define NSTEPS 12
#define NLABEL 10

typedef __half hf;

// ===================== small helpers ========================================
__device__ __forceinline__ uint32_t smem_u32(const void* p) {
    uint32_t a;
    asm("{ .reg .u64 t; cvta.to.shared.u64 t, %1; cvt.u32.u64 %0, t; }" : "=r"(a) : "l"(p));
    return a;
}
__device__ __forceinline__ void cp16(uint32_t dst, const void* src) {
    asm volatile("cp.async.cg.shared.global [%0], [%1], 16;" :: "r"(dst), "l"(src) : "memory");
}
__device__ __forceinline__ void ldm4(uint32_t* r, uint32_t addr) {
    asm volatile("ldmatrix.sync.aligned.m8n8.x4.shared.b16 {%0,%1,%2,%3}, [%4];"
        : "=r"(r[0]), "=r"(r[1]), "=r"(r[2]), "=r"(r[3]) : "r"(addr));
}
// fp16-accumulator MMA: D(f16x2 pair) = A*B + 0. Result drained to fp32 by caller.
__device__ __forceinline__ void mma16816h(uint32_t* d, const uint32_t* a, const uint32_t* b) {
    asm volatile("mma.sync.aligned.m16n8k16.row.col.f16.f16.f16.f16 "
        "{%0,%1}, {%2,%3,%4,%5}, {%6,%7}, {%8,%9};"
        : "=r"(d[0]), "=r"(d[1])
        : "r"(a[0]), "r"(a[1]), "r"(a[2]), "r"(a[3]), "r"(b[0]), "r"(b[1]),
          "r"(0u), "r"(0u));
}
__device__ __forceinline__ float sigf(float x) { return 1.f / (1.f + expf(-x)); }
__device__ __forceinline__ void hsplit(float v, hf* H, hf* L) {
    hf h = __float2half_rn(v);
    *H = h;
    *L = __float2half_rn(v - __half2float(h));
}

// ===================== device scratch =======================================
#define DGF(name, n) static __device__ __align__(128) float name[n]
#define DGH(name, n) static __device__ __align__(128) hf    name[n]
DGH(g_wmix_hi, 512*1536);    DGH(g_wmix_lo, 512*1536);
DGH(g_win_hi,  Ss*512*1024); DGH(g_win_lo,  Ss*512*1024);
DGH(g_wlink_hi,Ss*512*512);
DGH(g_wih_hi,  Ss*1536*512);
DGH(g_whh_hi,  Ss*1536*512);
DGH(g_wdel_hi, Ss*512*512);
DGH(g_cathi, Bb*1536); DGH(g_catlo, Bb*1536);
DGF(g_h,   Bb*Ww);  DGH(g_hhi, Bb*Ww);  DGH(g_hlo, Bb*Ww);
DGH(g_pre, Ss*Bb*Ww);
DGH(g_f0hi, Ss*Bb*Ww);
DGH(g_fthi, Ss*Bb*Ww);
DGH(g_rz,   Ss*Bb*1024);         // summed r,z logits
DGH(g_gin,  Ss*Bb*Ww);           // gi n-part
DGH(g_ghn,  Ss*Bb*Ww);           // gh n-part
DGH(g_hshi, Ss*Bb*Ww);
DGH(g_f2hi, Ss*Bb*Ww);
DGH(g_upd,  Ss*Bb*Ww);
DGF(g_gate, Ss*Bb);
DGF(g_gain, Ss*Ww);
DGF(g_brz,  Ss*1024);            // combined rz bias
DGF(g_part, 8*Bb*Ww);            // split-K partials for the summary GEMM

// ===================== mma.sync fp16 split GEMM =============================
// CTA tile 128x128, 4 warps of 64x64. 4-stage cp.async pipeline, K-stage 32.
// MMA uses fp16 accumulators per k16 chunk, drained immediately into fp32
// register accumulators (rate experiment; precision cost ~1e-4).
// terms=1: (Ah,Bh). terms=2: +(Al,Bh) or +(Al,Bl) if abPair. terms=3: +(Ah,Bl).
// Dual-problem: A2hi set -> z>=8 uses second pointer set + OWN geometry.
// Split-K: kSplit>1 -> z is the K-slice index; raw fp32 partials to Cpart.
static constexpr int STG_BYTES = 16384;
static constexpr int SMEM_DYN = 4 * STG_BYTES;

struct TG {
    const hf *Ahi, *Alo, *Bhi, *Blo;
    const hf *A2hi, *B2hi;
    const float *bias, *bias2, *gate;
    const hf *DresH;                  // problem-1 fp16 residual
    float* C; hf* Cf; hf* C2f; hf *Chi, *Clo;
    float* Cpart;
    long long aBatch, bBatch, aBatch2, bBatch2;
    long long biasBatch, bias2Batch, dBatch, cBatch, cBatch2;
    int lda, ldb, lda2, ldb2, ldd, ldc, ldc2;
    int K, aRot, act, act2, terms, terms2, kSplit, abPair, nx2;
    float scale;
};

__global__ void __launch_bounds__(128, 2) tgemm(TG g) {
    extern __shared__ __align__(16) char dyn[];
    uint32_t smem = smem_u32(dyn);
    int tid = threadIdx.x, wid = tid >> 5, lane = tid & 31;
    int z = blockIdx.z;

    bool second = (g.A2hi != nullptr) && (z >= 8);
    if (second && blockIdx.x >= g.nx2) return;

    const hf* Ahi_ = second ? g.A2hi : g.Ahi;
    const hf* Bhi_ = second ? g.B2hi : g.Bhi;
    const float* bias_ = second ? g.bias2 : g.bias;
    hf* Cf_ = second ? g.C2f : g.Cf;
    int myTerms = second ? g.terms2 : g.terms;
    int myAct   = second ? g.act2 : g.act;
    int myLda   = second ? g.lda2 : g.lda;
    int myLdb   = second ? g.ldb2 : g.ldb;
    int myLdc   = second ? g.ldc2 : g.ldc;
    long long myABatch = second ? g.aBatch2 : g.aBatch;
    long long myBBatch = second ? g.bBatch2 : g.bBatch;
    long long myCBatch = second ? g.cBatch2 : g.cBatch;
    long long myBiasB  = second ? g.bias2Batch : g.biasBatch;
    long long zz = second ? z - 8 : z;
    int nz = g.A2hi ? 8 : (int)gridDim.z;

    const int NKR = g.K >> 5;
    int NKtot = NKR * myTerms;
    int s0 = 0, NKl = NKtot;
    if (g.kSplit > 1) { zz = 0; NKl = NKtot / g.kSplit; s0 = z * NKl; }

    long long az = g.aRot ? (zz + nz - 1) % nz : zz;
    int m0 = blockIdx.y * 128, n0 = blockIdx.x * 128;

    const hf* Ah = Ahi_ + az * myABatch + (long long)m0 * myLda;
    const hf* Al = g.Alo ? g.Alo + az * g.aBatch + (long long)m0 * g.lda : Ah;
    const hf* Bh = Bhi_ + zz * myBBatch + (long long)n0 * myLdb;
    const hf* Bl = g.Blo ? g.Blo + zz * g.bBatch + (long long)n0 * g.ldb : Bh;

    auto issue = [&](int kt) {
        if (kt < NKl) {
            int abs = kt + s0;
            int region = (abs >= 2*NKR) ? 2 : (abs >= NKR ? 1 : 0);
            int kk = (abs - region * NKR) << 5;
            const hf* Ap = (region == 1) ? Al : Ah;
            const hf* Bp = (region == 2 || (g.abPair && region == 1)) ? Bl : Bh;
            int ldA = (region == 1) ? g.lda : myLda;
            int ldB = (region == 2 || (g.abPair && region == 1)) ? g.ldb : myLdb;
            uint32_t sb = smem + (uint32_t)(kt & 3) * STG_BYTES;
#pragma unroll
            for (int t = 0; t < 4; t++) {
                int gch = tid + t * 128;
                int r = gch >> 2, c = gch & 3;
                uint32_t sw = (uint32_t)(c ^ ((r >> 1) & 3)) << 4;
                cp16(sb + (uint32_t)r * 64 + sw, Ap + (long long)r * ldA + kk + c * 8);
                cp16(sb + 8192 + (uint32_t)r * 64 + sw, Bp + (long long)r * ldB + kk + c * 8);
            }
        }
        asm volatile("cp.async.commit_group;" ::: "memory");
    };

    issue(0); issue(1); issue(2);

    int wm = (wid & 1) * 64, wn = (wid >> 1) * 64;
    float acc[4][8][4];
#pragma unroll
    for (int i = 0; i < 4; i++)
#pragma unroll
        for (int n = 0; n < 8; n++)
#pragma unroll
            for (int q = 0; q < 4; q++) acc[i][n][q] = 0.f;

    for (int kt = 0; kt < NKl; kt++) {
        asm volatile("cp.async.wait_group 2;" ::: "memory");
        __syncthreads();
        issue(kt + 3);

        uint32_t sb = smem + (uint32_t)(kt & 3) * STG_BYTES;
#pragma unroll
        for (int j = 0; j < 2; j++) {
            uint32_t a[4][4], b2[8][2];
#pragma unroll
            for (int i = 0; i < 4; i++) {
                int r = wm + i * 16 + (lane & 15);
                int ch = j * 2 + (lane >> 4);
                uint32_t addr = sb + (uint32_t)r * 64 + ((uint32_t)(ch ^ ((r >> 1) & 3)) << 4);
                ldm4(a[i], addr);
            }
#pragma unroll
            for (int p = 0; p < 4; p++) {
                int r = wn + p * 16 + ((lane >> 4) << 3) + (lane & 7);
                int ch = j * 2 + ((lane >> 3) & 1);
                uint32_t addr = sb + 8192 + (uint32_t)r * 64 + ((uint32_t)(ch ^ ((r >> 1) & 3)) << 4);
                uint32_t rr[4];
                ldm4(rr, addr);
                b2[2*p][0] = rr[0]; b2[2*p][1] = rr[1];
                b2[2*p+1][0] = rr[2]; b2[2*p+1][1] = rr[3];
            }
#pragma unroll
            for (int i = 0; i < 4; i++)
#pragma unroll
                for (int n = 0; n < 8; n++) {
                    uint32_t d[2];
                    mma16816h(d, a[i], b2[n]);
                    float2 lo = __half22float2(*(__half2*)&d[0]);
                    float2 hi = __half22float2(*(__half2*)&d[1]);
                    acc[i][n][0] += lo.x; acc[i][n][1] += lo.y;
                    acc[i][n][2] += hi.x; acc[i][n][3] += hi.y;
                }
        }
    }

    // ---- epilogue ----
    const float* biasp = bias_ ? bias_ + zz * myBiasB + n0 : nullptr;
#pragma unroll
    for (int i = 0; i < 4; i++) {
#pragma unroll
        for (int half = 0; half < 2; half++) {
            int row = wm + i * 16 + (lane >> 2) + half * 8;
            long long grow = m0 + row;
            if (g.Cpart) {
                float* Pp = g.Cpart + (long long)z * g.cBatch + grow * g.ldc + n0;
#pragma unroll
                for (int nt = 0; nt < 8; nt++) {
                    int col = wn + nt * 8 + (lane & 3) * 2;
                    *(float2*)(Pp + col) =
                        make_float2(acc[i][nt][half*2], acc[i][nt][half*2+1]);
                }
                continue;
            }
            float gmul = g.scale;
            if (!second && g.gate) gmul *= g.gate[zz * Bb + grow];
            const hf* Dp = (!second && g.DresH) ?
                g.DresH + zz * g.dBatch + grow * g.ldd + n0 : nullptr;
            float* Cp  = (!second && g.C)   ? g.C   + zz * myCBatch + grow * myLdc + n0 : nullptr;
            hf* Cfp    = Cf_   ? Cf_   + zz * myCBatch + grow * myLdc + n0 : nullptr;
            hf* Chp    = (!second && g.Chi) ? g.Chi + zz * myCBatch + grow * myLdc + n0 : nullptr;
            hf* Clp    = (!second && g.Clo) ? g.Clo + zz * myCBatch + grow * myLdc + n0 : nullptr;
#pragma unroll
            for (int nt = 0; nt < 8; nt++) {
                int col = wn + nt * 8 + (lane & 3) * 2;
                float v0 = acc[i][nt][half * 2 + 0];
                float v1 = acc[i][nt][half * 2 + 1];
                if (biasp) { v0 += biasp[col]; v1 += biasp[col + 1]; }
                if (Dp) {
                    __half2 d = *(const __half2*)(Dp + col);
                    v0 += __half2float(__low2half(d));
                    v1 += __half2float(__high2half(d));
                }
                if (myAct) { v0 = tanhf(v0);   v1 = tanhf(v1); }
                v0 *= gmul; v1 *= gmul;
                if (Cp)  *(float2*)(Cp + col) = make_float2(v0, v1);
                if (Cfp) *(__half2*)(Cfp + col) = __halves2half2(__float2half_rn(v0), __float2half_rn(v1));
                if (Chp) {
                    hf h0 = __float2half_rn(v0), h1 = __float2half_rn(v1);
                    hf l0 = __float2half_rn(v0 - __half2float(h0));
                    hf l1 = __float2half_rn(v1 - __half2float(h1));
                    *(__half2*)(Chp + col) = __halves2half2(h0, h1);
                    *(__half2*)(Clp + col) = __halves2half2(l0, l1);
                }
            }
        }
    }
}

// ===================== prep: weight conversions + state init ================
static constexpr long long P0 = 512*1536;
static constexpr long long P1 = P0 + (long long)Ss*512*1024;
static constexpr long long P2 = P1 + (long long)Ss*512*512;
static constexpr long long P3 = P2 + (long long)Ss*1536*512;
static constexpr long long P4 = P3 + (long long)Ss*1536*512;
static constexpr long long P5 = P4 + (long long)Ss*512*512;
static constexpr long long P6 = P5 + (long long)Ss*Bb*Ww;
static constexpr long long P7 = P6 + Ss*Ww;
static constexpr long long P8 = P7 + Ss*1024;
__global__ void prep_all(const float* __restrict__ wmix, const float* __restrict__ win,
                         const float* __restrict__ wlink, const float* __restrict__ wih,
                         const float* __restrict__ whh, const float* __restrict__ wdel,
                         const float* __restrict__ pgain,
                         const float* __restrict__ bih, const float* __restrict__ bhh) {
    long long i = ((long long)blockIdx.x * 256 + threadIdx.x) * 4;
    if (i >= P8) return;
    if (i < P1) {
        const float* src; hf *hi, *lo; long long off;
        if (i < P0) { src = wmix; hi = g_wmix_hi; lo = g_wmix_lo; off = i; }
        else        { src = win;  hi = g_win_hi;  lo = g_win_lo;  off = i - P0; }
        float4 v = *(const float4*)(src + off);
        hf H[4], L[4];
        hsplit(v.x, H+0, L+0); hsplit(v.y, H+1, L+1);
        hsplit(v.z, H+2, L+2); hsplit(v.w, H+3, L+3);
        *(__half2*)(hi + off)     = __halves2half2(H[0], H[1]);
        *(__half2*)(hi + off + 2) = __halves2half2(H[2], H[3]);
        *(__half2*)(lo + off)     = __halves2half2(L[0], L[1]);
        *(__half2*)(lo + off + 2) = __halves2half2(L[2], L[3]);
    } else if (i < P5) {
        const float* src; hf* dst; long long off;
        if (i < P3)      { src = (i < P2) ? wlink : wih;
                           dst = (i < P2) ? g_wlink_hi : g_wih_hi;
                           off = (i < P2) ? i - P1 : i - P2; }
        else             { src = (i < P4) ? whh : wdel;
                           dst = (i < P4) ? g_whh_hi : g_wdel_hi;
                           off = (i < P4) ? i - P3 : i - P4; }
        float4 v = *(const float4*)(src + off);
        *(__half2*)(dst + off)     = __halves2half2(__float2half_rn(v.x), __float2half_rn(v.y));
        *(__half2*)(dst + off + 2) = __halves2half2(__float2half_rn(v.z), __float2half_rn(v.w));
    } else if (i < P6) {
        long long off = i - P5;
        *(__half2*)(g_hshi + off)     = __halves2half2(__float2half_rn(0.f), __float2half_rn(0.f));
        *(__half2*)(g_hshi + off + 2) = __halves2half2(__float2half_rn(0.f), __float2half_rn(0.f));
    } else if (i < P7) {
        long long off = i - P6;
        float4 v = *(const float4*)(pgain + off);
        float o[4] = {v.x, v.y, v.z, v.w};
#pragma unroll
        for (int k = 0; k < 4; k++)
            o[k] = o[k] > 20.f ? o[k] : log1pf(expf(o[k]));
        *(float4*)(g_gain + off) = make_float4(o[0], o[1], o[2], o[3]);
    } else {
        long long off = i - P7;
        long long s = off >> 10, j = off & 1023;
        float4 a = *(const float4*)(bih + s*1536 + j);
        float4 b = *(const float4*)(bhh + s*1536 + j);
        *(float4*)(g_brz + off) = make_float4(a.x+b.x, a.y+b.y, a.z+b.z, a.w+b.w);
    }
}

__global__ void encode_kernel(const int* __restrict__ x, const float* __restrict__ embed) {
    int b = blockIdx.x, t = threadIdx.x;
    __shared__ int sx[Ll];
    sx[t] = x[b*Ll + t];
    __syncthreads();
    float sm[4] = {0,0,0,0};
    float mx[4] = {-10000.f,-10000.f,-10000.f,-10000.f};
    int cnt = 0;
    for (int l = 0; l < Ll; l++) {
        int tok = sx[l];
        if (tok != 0) {
            cnt++;
            const float* e = embed + tok*Ww;
#pragma unroll
            for (int q = 0; q < 4; q++) {
                float v = e[t + q*128];
                sm[q] += v; mx[q] = fmaxf(mx[q], v);
            }
        }
    }
    float denom = (float)(cnt > 0 ? cnt : 1);
    int li = cnt > 0 ? cnt - 1 : 0;
    const float* le = embed + sx[li]*Ww;
    long long base = (long long)b * 1536;
#pragma unroll
    for (int q = 0; q < 4; q++) {
        int w = t + q*128;
        float vals[3] = { sm[q]/denom, mx[q], le[w] };
#pragma unroll
        for (int j = 0; j < 3; j++) {
            long long idx = base + j*Ww + w;
            hsplit(vals[j], g_cathi + idx, g_catlo + idx);
        }
    }
}

__global__ void sum_finalize(const float* __restrict__ bias) {
    int i = blockIdx.x*256 + threadIdx.x;
    const long long BW = (long long)Bb*Ww;
    float v = bias[i & 511];
#pragma unroll
    for (int k = 0; k < 8; k++) v += g_part[k*BW + i];
    v = tanhf(v);
    g_h[i] = v;
    hsplit(v, g_hhi + i, g_hlo + i);
}

// GRU combine (rz summed + separate n parts) + gate-dot + prism feat2
__global__ void gru_prism(const float* __restrict__ Wg, const float* __restrict__ bg,
                          const float* __restrict__ phase) {
    int b = blockIdx.x, s = blockIdx.y, t = threadIdx.x;
    long long sb = (long long)s*Bb + b;
    const __half2* rzp = (const __half2*)(g_rz + sb*1024);
    const __half2* ginp = (const __half2*)(g_gin + sb*Ww);
    const __half2* ghnp = (const __half2*)(g_ghn + sb*Ww);
    __half2* hsh = (__half2*)(g_hshi + sb*Ww);
    __half2* f2p = (__half2*)(g_f2hi + sb*Ww);
    const float2* Wg2 = (const float2*)(Wg + s*Ww);
    const float2* ph2 = (const float2*)(phase + s*Ww);
    const float2* gn2 = (const float2*)(g_gain + s*Ww);
    float dot = 0.f;
#pragma unroll
    for (int q = 0; q < 2; q++) {
        int p = t + q*128;
        float2 rr = __half22float2(rzp[p]);
        float2 zv = __half22float2(rzp[256 + p]);
        float2 gn = __half22float2(ginp[p]);
        float2 hn = __half22float2(ghnp[p]);
        float2 ho = __half22float2(hsh[p]);
        float r0 = sigf(rr.x), r1 = sigf(rr.y);
        float z0 = sigf(zv.x), z1 = sigf(zv.y);
        float n0 = tanhf(gn.x + r0*hn.x), n1 = tanhf(gn.y + r1*hn.y);
        float hv0 = (1.f - z0)*n0 + z0*ho.x;
        float hv1 = (1.f - z1)*n1 + z1*ho.y;
        hsh[p] = __halves2half2(__float2half_rn(hv0), __float2half_rn(hv1));
        float2 wg = Wg2[p];
        dot += wg.x*hv0 + wg.y*hv1;
        float2 ph = ph2[p], ga = gn2[p];
        float c0 = cosf(hv0 + ph.x), c1 = cosf(hv1 + ph.y);
        f2p[p] = __halves2half2(__float2half_rn(c0*c0*ga.x),
                                __float2half_rn(c1*c1*ga.y));
    }
#pragma unroll
    for (int o = 16; o; o >>= 1) dot += __shfl_down_sync(0xffffffffu, dot, o);
    __shared__ float red[4];
    if ((t & 31) == 0) red[t>>5] = dot;
    __syncthreads();
    if (t == 0) g_gate[s*Bb + b] = sigf(red[0]+red[1]+red[2]+red[3] + bg[s]);
}

__global__ void h_update(const float* __restrict__ decay_param) {
    int i = (blockIdx.x*256 + threadIdx.x) * 2;
    float dec = sigf(decay_param[0]);
    float a0 = 0.f, a1 = 0.f;
#pragma unroll
    for (int s = 0; s < Ss; s++) {
        float2 u = __half22float2(*(const __half2*)(g_upd + (long long)s*Bb*Ww + i));
        a0 += u.x; a1 += u.y;
    }
    float2 hv2 = *(float2*)(g_h + i);
    float h0 = tanhf(hv2.x*dec + a0);
    float h1 = tanhf(hv2.y*dec + a1);
    *(float2*)(g_h + i) = make_float2(h0, h1);
    *(__half2*)(g_hhi + i) = __halves2half2(__float2half_rn(h0), __float2half_rn(h1));
}

__global__ void out_proj(const float* __restrict__ Wout, const float* __restrict__ bout,
                         float* __restrict__ out) {
    int b = blockIdx.x, j = threadIdx.y, lane = threadIdx.x;
    const float* hr = g_h + (long long)b*Ww;
    const float* wr = Wout + j*Ww;
    float acc = 0.f;
    for (int w = lane; w < Ww; w += 32) acc += hr[w]*wr[w];
#pragma unroll
    for (int o = 16; o; o >>= 1) acc += __shfl_down_sync(0xffffffffu, acc, o);
    if (lane == 0) out[b*NLABEL + j] = acc + bout[j];
}

// ===================== host orchestration ===================================
static inline TG mkTG() {
    TG a; __builtin_memset(&a, 0, sizeof(a));
    a.scale = 1.f; a.terms = 1; a.terms2 = 1; a.nx2 = 1 << 30;
    return a;
}

extern "C" void kernel_launch(void* const* d_in, const int* in_sizes, int n_in,
                              void* d_out, int out_size) {
    const int*   x       = (const int*)d_in[0];
    const float* embed   = (const float*)d_in[1];
    const float* W_mix   = (const float*)d_in[2];
    const float* b_mix   = (const float*)d_in[3];
    const float* W_in    = (const float*)d_in[4];
    const float* b_in    = (const float*)d_in[5];
    const float* W_link  = (const float*)d_in[6];
    const float* b_link  = (const float*)d_in[7];
    const float* W_ih    = (const float*)d_in[8];
    const float* b_ih    = (const float*)d_in[9];
    const float* W_hh    = (const float*)d_in[10];
    const float* b_hh    = (const float*)d_in[11];
    const float* W_gate  = (const float*)d_in[12];
    const float* b_gate  = (const float*)d_in[13];
    const float* phase   = (const float*)d_in[14];
    const float* pgain   = (const float*)d_in[15];
    const float* W_delta = (const float*)d_in[16];
    const float* b_delta = (const float*)d_in[17];
    const float* decay   = (const float*)d_in[18];
    const float* W_out   = (const float*)d_in[19];
    const float* b_out   = (const float*)d_in[20];

    cudaFuncSetAttribute(tgemm, cudaFuncAttributeMaxDynamicSharedMemorySize, SMEM_DYN);

#define SYMF(p, s) float* p; cudaGetSymbolAddress((void**)&p, s)
#define SYMH(p, s) hf*    p; cudaGetSymbolAddress((void**)&p, s)
    SYMH(wmixH, g_wmix_hi); SYMH(wmixL, g_wmix_lo);
    SYMH(winH, g_win_hi);   SYMH(winL, g_win_lo);
    SYMH(wlkH, g_wlink_hi);
    SYMH(wihH, g_wih_hi);
    SYMH(whhH, g_whh_hi);
    SYMH(wdlH, g_wdel_hi);
    SYMH(catH, g_cathi);    SYMH(catL, g_catlo);
    SYMF(h,  g_h); SYMH(hH, g_hhi); SYMH(hL, g_hlo);
    SYMH(preH, g_pre);
    SYMH(f0H, g_f0hi);
    SYMH(ftH, g_fthi);
    SYMH(rzH, g_rz); SYMH(ginH, g_gin); SYMH(ghnH, g_ghn);
    SYMH(hsH, g_hshi);
    SYMH(f2H, g_f2hi);
    SYMH(updH, g_upd); SYMF(gatep, g_gate);
    SYMF(brzP, g_brz);
    SYMF(partP, g_part);
#undef SYMF
#undef SYMH

    const long long BW = (long long)Bb*Ww;
    const float invs = 0.35355339059327373f;

    // ---- preamble (launch 5 = merged f0+ghn tgemm for ncu -s 5) -----------
    prep_all<<<(int)((P8/4 + 255)/256), 256>>>(W_mix, W_in, W_link, W_ih,
                                               W_hh, W_delta, pgain, b_ih, b_hh); // 0
    encode_kernel<<<Bb, 128>>>(x, embed);                                         // 1

    // 2: summary GEMM split-K x8
    {
        TG a = mkTG();
        a.Ahi = catH; a.Alo = catL; a.lda = 1536;
        a.Bhi = wmixH; a.Blo = wmixL; a.ldb = 1536;
        a.Cpart = partP; a.ldc = Ww; a.cBatch = BW;
        a.K = 1536; a.terms = 3; a.kSplit = 8;
        tgemm<<<dim3(4, 8, 8), 128, SMEM_DYN>>>(a);
    }
    sum_finalize<<<(Bb*Ww)/256, 256>>>(b_mix);                                    // 3

    // 4: pre[s] = summary @ W_in[s][:, W:]^T  (2-term)
    {
        TG a = mkTG();
        a.Ahi = hH; a.Alo = hL; a.lda = Ww;
        a.Bhi = winH + Ww; a.ldb = 2*Ww; a.bBatch = (long long)Ww*2*Ww;
        a.Cf = preH; a.ldc = Ww; a.cBatch = BW;
        a.K = Ww; a.terms = 2;
        tgemm<<<dim3(4, 8, Ss), 128, SMEM_DYN>>>(a);
    }

    // merged: z<8 f0 = tanh(h@Win[:, :W]^T + pre + b_in);
    //         z>=8 ghn = hs@Whh_n^T + b_hh_n   (own geometry)
    auto launch_f0_ghn = [&]() {
        TG a = mkTG();
        a.Ahi = hH; a.lda = Ww; a.aBatch = 0;
        a.Bhi = winH; a.ldb = 2*Ww; a.bBatch = (long long)Ww*2*Ww;
        a.bias = b_in; a.biasBatch = Ww;
        a.DresH = preH; a.ldd = Ww; a.dBatch = BW;
        a.Cf = f0H; a.ldc = Ww; a.cBatch = BW;
        a.act = 1;
        a.A2hi = hsH; a.lda2 = Ww; a.aBatch2 = BW;
        a.B2hi = whhH + (long long)1024*Ww; a.ldb2 = Ww; a.bBatch2 = (long long)3*Ww*Ww;
        a.bias2 = b_hh + 1024; a.bias2Batch = 3*Ww;
        a.C2f = ghnH; a.ldc2 = Ww; a.cBatch2 = BW;
        a.act2 = 0; a.nx2 = 4;
        a.K = Ww;
        tgemm<<<dim3(4, 8, 16), 128, SMEM_DYN>>>(a);
    };
    launch_f0_ghn();                                                              // 5

    for (int t = 0; t < NSTEPS; ++t) {
        if (t > 0) launch_f0_ghn();
        // feats = tanh(f0 + roll(f0) @ W_link^T + b_link)
        {
            TG a = mkTG();
            a.Ahi = f0H; a.lda = Ww; a.aBatch = BW; a.aRot = 1;
            a.Bhi = wlkH; a.ldb = Ww; a.bBatch = (long long)Ww*Ww;
            a.bias = b_link; a.biasBatch = Ww;
            a.DresH = f0H; a.ldd = Ww; a.dBatch = BW;
            a.Cf = ftH; a.ldc = Ww; a.cBatch = BW;
            a.K = Ww; a.act = 1;
            tgemm<<<dim3(4, 8, Ss), 128, SMEM_DYN>>>(a);
        }
        // merged: z<8 rz = feats@Wih_rz^T + hs@Whh_rz^T + brz;
        //         z>=8 gin = feats@Wih_n^T + b_ih_n (x<4)
        {
            TG a = mkTG();
            a.Ahi = ftH; a.Alo = hsH; a.lda = Ww; a.aBatch = BW;
            a.Bhi = wihH; a.Blo = whhH; a.ldb = Ww; a.bBatch = (long long)3*Ww*Ww;
            a.bias = brzP; a.biasBatch = 1024;
            a.Cf = rzH; a.ldc = 1024; a.cBatch = (long long)Bb*1024;
            a.terms = 2; a.abPair = 1;
            a.A2hi = ftH; a.lda2 = Ww; a.aBatch2 = BW;
            a.B2hi = wihH + (long long)1024*Ww; a.ldb2 = Ww; a.bBatch2 = (long long)3*Ww*Ww;
            a.bias2 = b_ih + 1024; a.bias2Batch = 3*Ww;
            a.C2f = ginH; a.ldc2 = Ww; a.cBatch2 = BW;
            a.terms2 = 1; a.nx2 = 4;
            a.K = Ww;
            tgemm<<<dim3(8, 8, 16), 128, SMEM_DYN>>>(a);
        }
        gru_prism<<<dim3(Bb, Ss), 128>>>(W_gate, b_gate, phase);
        // upd = gate * tanh(f2 @ W_delta^T + b_delta) * invs
        {
            TG a = mkTG();
            a.Ahi = f2H; a.lda = Ww; a.aBatch = BW;
            a.Bhi = wdlH; a.ldb = Ww; a.bBatch = (long long)Ww*Ww;
            a.bias = b_delta; a.biasBatch = Ww;
            a.gate = gatep;
            a.Cf = updH; a.ldc = Ww; a.cBatch = BW;
            a.K = Ww; a.act = 1; a.scale = invs;
            tgemm<<<dim3(4, 8, Ss), 128, SMEM_DYN>>>(a);
        }
        h_update<<<(Bb*Ww)/512, 256>>>(decay);
    }

    out_proj<<<Bb, dim3(32, NLABEL)>>>(W_out, b_out, (float*)d_out);
}

// round 15
// speedup vs baseline: 1.5110x; 1.5110x over previous
#include <cuda_runtime.h>
#include <cuda_fp16.h>
#include <cstdint>
#include <cmath>

#define Bb 1024
#define Ll 128
#define Ww 512
#define Ss 8
#define NSTEPS 12
#define NLABEL 10

typedef __half hf;

// ===================== small helpers ========================================
__device__ __forceinline__ uint32_t smem_u32(const void* p) {
    uint32_t a;
    asm("{ .reg .u64 t; cvta.to.shared.u64 t, %1; cvt.u32.u64 %0, t; }" : "=r"(a) : "l"(p));
    return a;
}
__device__ __forceinline__ void cp16(uint32_t dst, const void* src) {
    asm volatile("cp.async.cg.shared.global [%0], [%1], 16;" :: "r"(dst), "l"(src) : "memory");
}
__device__ __forceinline__ void ldm4(uint32_t* r, uint32_t addr) {
    asm volatile("ldmatrix.sync.aligned.m8n8.x4.shared.b16 {%0,%1,%2,%3}, [%4];"
        : "=r"(r[0]), "=r"(r[1]), "=r"(r[2]), "=r"(r[3]) : "r"(addr));
}
__device__ __forceinline__ void mma16816(float* c, const uint32_t* a, const uint32_t* b) {
    asm volatile("mma.sync.aligned.m16n8k16.row.col.f32.f16.f16.f32 "
        "{%0,%1,%2,%3}, {%4,%5,%6,%7}, {%8,%9}, {%0,%1,%2,%3};"
        : "+f"(c[0]), "+f"(c[1]), "+f"(c[2]), "+f"(c[3])
        : "r"(a[0]), "r"(a[1]), "r"(a[2]), "r"(a[3]), "r"(b[0]), "r"(b[1]));
}
__device__ __forceinline__ float sigf(float x) { return 1.f / (1.f + expf(-x)); }
__device__ __forceinline__ void hsplit(float v, hf* H, hf* L) {
    hf h = __float2half_rn(v);
    *H = h;
    *L = __float2half_rn(v - __half2float(h));
}

// ===================== device scratch =======================================
#define DGF(name, n) static __device__ __align__(128) float name[n]
#define DGH(name, n) static __device__ __align__(128) hf    name[n]
DGH(g_wmix_hi, 512*1536);    DGH(g_wmix_lo, 512*1536);
DGH(g_win_hi,  Ss*512*1024);
DGH(g_wlink_hi,Ss*512*512);
DGH(g_wih_hi,  Ss*1536*512);
DGH(g_whh_hi,  Ss*1536*512);
DGH(g_wdel_hi, Ss*512*512);
DGH(g_cathi, Bb*1536); DGH(g_catlo, Bb*1536);
DGF(g_h,   Bb*Ww);  DGH(g_hhi, Bb*Ww);
DGH(g_pre, Ss*Bb*Ww);
DGH(g_f0hi, Ss*Bb*Ww);
DGH(g_fthi, Ss*Bb*Ww);
DGH(g_rz,   Ss*Bb*1024);         // summed r,z logits
DGH(g_gin,  Ss*Bb*Ww);           // gi n-part
DGH(g_ghn,  Ss*Bb*Ww);           // gh n-part
DGH(g_hshi, Ss*Bb*Ww);
DGH(g_f2hi, Ss*Bb*Ww);
DGH(g_upd,  Ss*Bb*Ww);
DGF(g_gate, Ss*Bb);
DGF(g_gain, Ss*Ww);
DGF(g_brz,  Ss*1024);            // combined rz bias
DGF(g_part, 8*Bb*Ww);            // split-K partials for the summary GEMM

// ===================== mma.sync fp16 split GEMM =============================
// CTA tile 128x128, 4 warps of 64x64. 4-stage cp.async pipeline, K-stage 32.
// fp32 accumulators (f16-acc measured SLOWER on B300 legacy pipe, R14).
// terms=1: (Ah,Bh). terms=2: +(Al,Bh) or +(Al,Bl) if abPair. terms=3: +(Ah,Bl).
// Dual-problem: A2hi set -> z>=8 uses second pointer set + OWN geometry.
// Split-K: kSplit>1 -> z is the K-slice index; raw fp32 partials to Cpart.
static constexpr int STG_BYTES = 16384;
static constexpr int SMEM_DYN = 4 * STG_BYTES;

struct TG {
    const hf *Ahi, *Alo, *Bhi, *Blo;
    const hf *A2hi, *B2hi;
    const float *bias, *bias2, *gate;
    const hf *DresH;                  // problem-1 fp16 residual
    float* C; hf* Cf; hf* C2f;
    float* Cpart;
    long long aBatch, bBatch, aBatch2, bBatch2;
    long long biasBatch, bias2Batch, dBatch, cBatch, cBatch2;
    int lda, ldb, lda2, ldb2, ldd, ldc, ldc2;
    int K, aRot, act, act2, terms, terms2, kSplit, abPair, nx2;
    float scale;
};

__global__ void __launch_bounds__(128, 2) tgemm(TG g) {
    extern __shared__ __align__(16) char dyn[];
    uint32_t smem = smem_u32(dyn);
    int tid = threadIdx.x, wid = tid >> 5, lane = tid & 31;
    int z = blockIdx.z;

    bool second = (g.A2hi != nullptr) && (z >= 8);
    if (second && blockIdx.x >= g.nx2) return;

    const hf* Ahi_ = second ? g.A2hi : g.Ahi;
    const hf* Bhi_ = second ? g.B2hi : g.Bhi;
    const float* bias_ = second ? g.bias2 : g.bias;
    hf* Cf_ = second ? g.C2f : g.Cf;
    int myTerms = second ? g.terms2 : g.terms;
    int myAct   = second ? g.act2 : g.act;
    int myLda   = second ? g.lda2 : g.lda;
    int myLdb   = second ? g.ldb2 : g.ldb;
    int myLdc   = second ? g.ldc2 : g.ldc;
    long long myABatch = second ? g.aBatch2 : g.aBatch;
    long long myBBatch = second ? g.bBatch2 : g.bBatch;
    long long myCBatch = second ? g.cBatch2 : g.cBatch;
    long long myBiasB  = second ? g.bias2Batch : g.biasBatch;
    long long zz = second ? z - 8 : z;
    int nz = g.A2hi ? 8 : (int)gridDim.z;

    const int NKR = g.K >> 5;
    int NKtot = NKR * myTerms;
    int s0 = 0, NKl = NKtot;
    if (g.kSplit > 1) { zz = 0; NKl = NKtot / g.kSplit; s0 = z * NKl; }

    long long az = g.aRot ? (zz + nz - 1) % nz : zz;
    int m0 = blockIdx.y * 128, n0 = blockIdx.x * 128;

    const hf* Ah = Ahi_ + az * myABatch + (long long)m0 * myLda;
    const hf* Al = g.Alo ? g.Alo + az * g.aBatch + (long long)m0 * g.lda : Ah;
    const hf* Bh = Bhi_ + zz * myBBatch + (long long)n0 * myLdb;
    const hf* Bl = g.Blo ? g.Blo + zz * g.bBatch + (long long)n0 * g.ldb : Bh;

    auto issue = [&](int kt) {
        if (kt < NKl) {
            int abs = kt + s0;
            int region = (abs >= 2*NKR) ? 2 : (abs >= NKR ? 1 : 0);
            int kk = (abs - region * NKR) << 5;
            const hf* Ap = (region == 1) ? Al : Ah;
            const hf* Bp = (region == 2 || (g.abPair && region == 1)) ? Bl : Bh;
            int ldA = (region == 1) ? g.lda : myLda;
            int ldB = (region == 2 || (g.abPair && region == 1)) ? g.ldb : myLdb;
            uint32_t sb = smem + (uint32_t)(kt & 3) * STG_BYTES;
#pragma unroll
            for (int t = 0; t < 4; t++) {
                int gch = tid + t * 128;
                int r = gch >> 2, c = gch & 3;
                uint32_t sw = (uint32_t)(c ^ ((r >> 1) & 3)) << 4;
                cp16(sb + (uint32_t)r * 64 + sw, Ap + (long long)r * ldA + kk + c * 8);
                cp16(sb + 8192 + (uint32_t)r * 64 + sw, Bp + (long long)r * ldB + kk + c * 8);
            }
        }
        asm volatile("cp.async.commit_group;" ::: "memory");
    };

    issue(0); issue(1); issue(2);

    int wm = (wid & 1) * 64, wn = (wid >> 1) * 64;
    float acc[4][8][4];
#pragma unroll
    for (int i = 0; i < 4; i++)
#pragma unroll
        for (int n = 0; n < 8; n++)
#pragma unroll
            for (int q = 0; q < 4; q++) acc[i][n][q] = 0.f;

    for (int kt = 0; kt < NKl; kt++) {
        asm volatile("cp.async.wait_group 2;" ::: "memory");
        __syncthreads();
        issue(kt + 3);

        uint32_t sb = smem + (uint32_t)(kt & 3) * STG_BYTES;
#pragma unroll
        for (int j = 0; j < 2; j++) {
            uint32_t a[4][4], b2[8][2];
#pragma unroll
            for (int i = 0; i < 4; i++) {
                int r = wm + i * 16 + (lane & 15);
                int ch = j * 2 + (lane >> 4);
                uint32_t addr = sb + (uint32_t)r * 64 + ((uint32_t)(ch ^ ((r >> 1) & 3)) << 4);
                ldm4(a[i], addr);
            }
#pragma unroll
            for (int p = 0; p < 4; p++) {
                int r = wn + p * 16 + ((lane >> 4) << 3) + (lane & 7);
                int ch = j * 2 + ((lane >> 3) & 1);
                uint32_t addr = sb + 8192 + (uint32_t)r * 64 + ((uint32_t)(ch ^ ((r >> 1) & 3)) << 4);
                uint32_t rr[4];
                ldm4(rr, addr);
                b2[2*p][0] = rr[0]; b2[2*p][1] = rr[1];
                b2[2*p+1][0] = rr[2]; b2[2*p+1][1] = rr[3];
            }
#pragma unroll
            for (int i = 0; i < 4; i++)
#pragma unroll
                for (int n = 0; n < 8; n++)
                    mma16816(acc[i][n], a[i], b2[n]);
        }
    }

    // ---- epilogue ----
    const float* biasp = bias_ ? bias_ + zz * myBiasB + n0 : nullptr;
#pragma unroll
    for (int i = 0; i < 4; i++) {
#pragma unroll
        for (int half = 0; half < 2; half++) {
            int row = wm + i * 16 + (lane >> 2) + half * 8;
            long long grow = m0 + row;
            if (g.Cpart) {
                float* Pp = g.Cpart + (long long)z * g.cBatch + grow * g.ldc + n0;
#pragma unroll
                for (int nt = 0; nt < 8; nt++) {
                    int col = wn + nt * 8 + (lane & 3) * 2;
                    *(float2*)(Pp + col) =
                        make_float2(acc[i][nt][half*2], acc[i][nt][half*2+1]);
                }
                continue;
            }
            float gmul = g.scale;
            if (!second && g.gate) gmul *= g.gate[zz * Bb + grow];
            const hf* Dp = (!second && g.DresH) ?
                g.DresH + zz * g.dBatch + grow * g.ldd + n0 : nullptr;
            float* Cp  = (!second && g.C)   ? g.C   + zz * myCBatch + grow * myLdc + n0 : nullptr;
            hf* Cfp    = Cf_   ? Cf_   + zz * myCBatch + grow * myLdc + n0 : nullptr;
#pragma unroll
            for (int nt = 0; nt < 8; nt++) {
                int col = wn + nt * 8 + (lane & 3) * 2;
                float v0 = acc[i][nt][half * 2 + 0];
                float v1 = acc[i][nt][half * 2 + 1];
                if (biasp) { v0 += biasp[col]; v1 += biasp[col + 1]; }
                if (Dp) {
                    __half2 d = *(const __half2*)(Dp + col);
                    v0 += __half2float(__low2half(d));
                    v1 += __half2float(__high2half(d));
                }
                if (myAct) { v0 = tanhf(v0);   v1 = tanhf(v1); }
                v0 *= gmul; v1 *= gmul;
                if (Cp)  *(float2*)(Cp + col) = make_float2(v0, v1);
                if (Cfp) *(__half2*)(Cfp + col) = __halves2half2(__float2half_rn(v0), __float2half_rn(v1));
            }
        }
    }
}

// ===================== prep: weight conversions + state init ================
static constexpr long long P0 = 512*1536;                     // Wmix 2-way
static constexpr long long P1 = P0 + (long long)Ss*512*1024;  // Win 1-way
static constexpr long long P2 = P1 + (long long)Ss*512*512;   // link
static constexpr long long P3 = P2 + (long long)Ss*1536*512;  // ih
static constexpr long long P4 = P3 + (long long)Ss*1536*512;  // hh
static constexpr long long P5 = P4 + (long long)Ss*512*512;   // delta
static constexpr long long P6 = P5 + (long long)Ss*Bb*Ww;     // hs zero
static constexpr long long P7 = P6 + Ss*Ww;                   // gain
static constexpr long long P8 = P7 + Ss*1024;                 // brz
__global__ void prep_all(const float* __restrict__ wmix, const float* __restrict__ win,
                         const float* __restrict__ wlink, const float* __restrict__ wih,
                         const float* __restrict__ whh, const float* __restrict__ wdel,
                         const float* __restrict__ pgain,
                         const float* __restrict__ bih, const float* __restrict__ bhh) {
    long long i = ((long long)blockIdx.x * 256 + threadIdx.x) * 4;
    if (i >= P8) return;
    if (i < P0) {                                  // Wmix 2-way split
        float4 v = *(const float4*)(wmix + i);
        hf H[4], L[4];
        hsplit(v.x, H+0, L+0); hsplit(v.y, H+1, L+1);
        hsplit(v.z, H+2, L+2); hsplit(v.w, H+3, L+3);
        *(__half2*)(g_wmix_hi + i)     = __halves2half2(H[0], H[1]);
        *(__half2*)(g_wmix_hi + i + 2) = __halves2half2(H[2], H[3]);
        *(__half2*)(g_wmix_lo + i)     = __halves2half2(L[0], L[1]);
        *(__half2*)(g_wmix_lo + i + 2) = __halves2half2(L[2], L[3]);
    } else if (i < P5) {                           // 1-way converts
        const float* src; hf* dst; long long off;
        if (i < P2)      { src = (i < P1) ? win : wlink;
                           dst = (i < P1) ? g_win_hi : g_wlink_hi;
                           off = (i < P1) ? i - P0 : i - P1; }
        else if (i < P4) { src = (i < P3) ? wih : whh;
                           dst = (i < P3) ? g_wih_hi : g_whh_hi;
                           off = (i < P3) ? i - P2 : i - P3; }
        else             { src = wdel; dst = g_wdel_hi; off = i - P4; }
        float4 v = *(const float4*)(src + off);
        *(__half2*)(dst + off)     = __halves2half2(__float2half_rn(v.x), __float2half_rn(v.y));
        *(__half2*)(dst + off + 2) = __halves2half2(__float2half_rn(v.z), __float2half_rn(v.w));
    } else if (i < P6) {                           // hs zero
        long long off = i - P5;
        *(__half2*)(g_hshi + off)     = __halves2half2(__float2half_rn(0.f), __float2half_rn(0.f));
        *(__half2*)(g_hshi + off + 2) = __halves2half2(__float2half_rn(0.f), __float2half_rn(0.f));
    } else if (i < P7) {                           // softplus gain
        long long off = i - P6;
        float4 v = *(const float4*)(pgain + off);
        float o[4] = {v.x, v.y, v.z, v.w};
#pragma unroll
        for (int k = 0; k < 4; k++)
            o[k] = o[k] > 20.f ? o[k] : log1pf(expf(o[k]));
        *(float4*)(g_gain + off) = make_float4(o[0], o[1], o[2], o[3]);
    } else {                                       // combined rz bias
        long long off = i - P7;
        long long s = off >> 10, j = off & 1023;
        float4 a = *(const float4*)(bih + s*1536 + j);
        float4 b = *(const float4*)(bhh + s*1536 + j);
        *(float4*)(g_brz + off) = make_float4(a.x+b.x, a.y+b.y, a.z+b.z, a.w+b.w);
    }
}

__global__ void encode_kernel(const int* __restrict__ x, const float* __restrict__ embed) {
    int b = blockIdx.x, t = threadIdx.x;
    __shared__ int sx[Ll];
    sx[t] = x[b*Ll + t];
    __syncthreads();
    float sm[4] = {0,0,0,0};
    float mx[4] = {-10000.f,-10000.f,-10000.f,-10000.f};
    int cnt = 0;
    for (int l = 0; l < Ll; l++) {
        int tok = sx[l];
        if (tok != 0) {
            cnt++;
            const float* e = embed + tok*Ww;
#pragma unroll
            for (int q = 0; q < 4; q++) {
                float v = e[t + q*128];
                sm[q] += v; mx[q] = fmaxf(mx[q], v);
            }
        }
    }
    float denom = (float)(cnt > 0 ? cnt : 1);
    int li = cnt > 0 ? cnt - 1 : 0;
    const float* le = embed + sx[li]*Ww;
    long long base = (long long)b * 1536;
#pragma unroll
    for (int q = 0; q < 4; q++) {
        int w = t + q*128;
        float vals[3] = { sm[q]/denom, mx[q], le[w] };
#pragma unroll
        for (int j = 0; j < 3; j++) {
            long long idx = base + j*Ww + w;
            hsplit(vals[j], g_cathi + idx, g_catlo + idx);
        }
    }
}

__global__ void sum_finalize(const float* __restrict__ bias) {
    int i = blockIdx.x*256 + threadIdx.x;
    const long long BW = (long long)Bb*Ww;
    float v = bias[i & 511];
#pragma unroll
    for (int k = 0; k < 8; k++) v += g_part[k*BW + i];
    v = tanhf(v);
    g_h[i] = v;
    g_hhi[i] = __float2half_rn(v);
}

// GRU combine (rz summed + separate n parts) + gate-dot + prism feat2
__global__ void gru_prism(const float* __restrict__ Wg, const float* __restrict__ bg,
                          const float* __restrict__ phase) {
    int b = blockIdx.x, s = blockIdx.y, t = threadIdx.x;
    long long sb = (long long)s*Bb + b;
    const __half2* rzp = (const __half2*)(g_rz + sb*1024);
    const __half2* ginp = (const __half2*)(g_gin + sb*Ww);
    const __half2* ghnp = (const __half2*)(g_ghn + sb*Ww);
    __half2* hsh = (__half2*)(g_hshi + sb*Ww);
    __half2* f2p = (__half2*)(g_f2hi + sb*Ww);
    const float2* Wg2 = (const float2*)(Wg + s*Ww);
    const float2* ph2 = (const float2*)(phase + s*Ww);
    const float2* gn2 = (const float2*)(g_gain + s*Ww);
    float dot = 0.f;
#pragma unroll
    for (int q = 0; q < 2; q++) {
        int p = t + q*128;
        float2 rr = __half22float2(rzp[p]);
        float2 zv = __half22float2(rzp[256 + p]);
        float2 gn = __half22float2(ginp[p]);
        float2 hn = __half22float2(ghnp[p]);
        float2 ho = __half22float2(hsh[p]);
        float r0 = sigf(rr.x), r1 = sigf(rr.y);
        float z0 = sigf(zv.x), z1 = sigf(zv.y);
        float n0 = tanhf(gn.x + r0*hn.x), n1 = tanhf(gn.y + r1*hn.y);
        float hv0 = (1.f - z0)*n0 + z0*ho.x;
        float hv1 = (1.f - z1)*n1 + z1*ho.y;
        hsh[p] = __halves2half2(__float2half_rn(hv0), __float2half_rn(hv1));
        float2 wg = Wg2[p];
        dot += wg.x*hv0 + wg.y*hv1;
        float2 ph = ph2[p], ga = gn2[p];
        float c0 = cosf(hv0 + ph.x), c1 = cosf(hv1 + ph.y);
        f2p[p] = __halves2half2(__float2half_rn(c0*c0*ga.x),
                                __float2half_rn(c1*c1*ga.y));
    }
#pragma unroll
    for (int o = 16; o; o >>= 1) dot += __shfl_down_sync(0xffffffffu, dot, o);
    __shared__ float red[4];
    if ((t & 31) == 0) red[t>>5] = dot;
    __syncthreads();
    if (t == 0) g_gate[s*Bb + b] = sigf(red[0]+red[1]+red[2]+red[3] + bg[s]);
}

__global__ void h_update(const float* __restrict__ decay_param) {
    int i = (blockIdx.x*256 + threadIdx.x) * 2;
    float dec = sigf(decay_param[0]);
    float a0 = 0.f, a1 = 0.f;
#pragma unroll
    for (int s = 0; s < Ss; s++) {
        float2 u = __half22float2(*(const __half2*)(g_upd + (long long)s*Bb*Ww + i));
        a0 += u.x; a1 += u.y;
    }
    float2 hv2 = *(float2*)(g_h + i);
    float h0 = tanhf(hv2.x*dec + a0);
    float h1 = tanhf(hv2.y*dec + a1);
    *(float2*)(g_h + i) = make_float2(h0, h1);
    *(__half2*)(g_hhi + i) = __halves2half2(__float2half_rn(h0), __float2half_rn(h1));
}

// final step: h update fused with output projection (one block per batch row)
__global__ void h_final(const float* __restrict__ decay_param,
                        const float* __restrict__ Wout, const float* __restrict__ bout,
                        float* __restrict__ out) {
    int b = blockIdx.x, t = threadIdx.x;          // 256 threads, 2 elems each
    float dec = sigf(decay_param[0]);
    long long i = (long long)b*Ww + t*2;
    float a0 = 0.f, a1 = 0.f;
#pragma unroll
    for (int s = 0; s < Ss; s++) {
        float2 u = __half22float2(*(const __half2*)(g_upd + (long long)s*Bb*Ww + i));
        a0 += u.x; a1 += u.y;
    }
    float2 hv2 = *(float2*)(g_h + i);
    float h0 = tanhf(hv2.x*dec + a0);
    float h1 = tanhf(hv2.y*dec + a1);
    float acc[NLABEL];
#pragma unroll
    for (int j = 0; j < NLABEL; j++)
        acc[j] = h0*Wout[j*Ww + t*2] + h1*Wout[j*Ww + t*2 + 1];
#pragma unroll
    for (int o = 16; o; o >>= 1)
#pragma unroll
        for (int j = 0; j < NLABEL; j++)
            acc[j] += __shfl_down_sync(0xffffffffu, acc[j], o);
    __shared__ float red[8][NLABEL];
    if ((t & 31) == 0)
#pragma unroll
        for (int j = 0; j < NLABEL; j++) red[t>>5][j] = acc[j];
    __syncthreads();
    if (t < NLABEL) {
        float s = bout[t];
#pragma unroll
        for (int w = 0; w < 8; w++) s += red[w][t];
        out[b*NLABEL + t] = s;
    }
}

// ===================== host orchestration ===================================
static inline TG mkTG() {
    TG a; __builtin_memset(&a, 0, sizeof(a));
    a.scale = 1.f; a.terms = 1; a.terms2 = 1; a.nx2 = 1 << 30;
    return a;
}

extern "C" void kernel_launch(void* const* d_in, const int* in_sizes, int n_in,
                              void* d_out, int out_size) {
    const int*   x       = (const int*)d_in[0];
    const float* embed   = (const float*)d_in[1];
    const float* W_mix   = (const float*)d_in[2];
    const float* b_mix   = (const float*)d_in[3];
    const float* W_in    = (const float*)d_in[4];
    const float* b_in    = (const float*)d_in[5];
    const float* W_link  = (const float*)d_in[6];
    const float* b_link  = (const float*)d_in[7];
    const float* W_ih    = (const float*)d_in[8];
    const float* b_ih    = (const float*)d_in[9];
    const float* W_hh    = (const float*)d_in[10];
    const float* b_hh    = (const float*)d_in[11];
    const float* W_gate  = (const float*)d_in[12];
    const float* b_gate  = (const float*)d_in[13];
    const float* phase   = (const float*)d_in[14];
    const float* pgain   = (const float*)d_in[15];
    const float* W_delta = (const float*)d_in[16];
    const float* b_delta = (const float*)d_in[17];
    const float* decay   = (const float*)d_in[18];
    const float* W_out   = (const float*)d_in[19];
    const float* b_out   = (const float*)d_in[20];

    cudaFuncSetAttribute(tgemm, cudaFuncAttributeMaxDynamicSharedMemorySize, SMEM_DYN);

#define SYMF(p, s) float* p; cudaGetSymbolAddress((void**)&p, s)
#define SYMH(p, s) hf*    p; cudaGetSymbolAddress((void**)&p, s)
    SYMH(wmixH, g_wmix_hi); SYMH(wmixL, g_wmix_lo);
    SYMH(winH, g_win_hi);
    SYMH(wlkH, g_wlink_hi);
    SYMH(wihH, g_wih_hi);
    SYMH(whhH, g_whh_hi);
    SYMH(wdlH, g_wdel_hi);
    SYMH(catH, g_cathi);    SYMH(catL, g_catlo);
    SYMF(h,  g_h); SYMH(hH, g_hhi);
    SYMH(preH, g_pre);
    SYMH(f0H, g_f0hi);
    SYMH(ftH, g_fthi);
    SYMH(rzH, g_rz); SYMH(ginH, g_gin); SYMH(ghnH, g_ghn);
    SYMH(hsH, g_hshi);
    SYMH(f2H, g_f2hi);
    SYMH(updH, g_upd); SYMF(gatep, g_gate);
    SYMF(brzP, g_brz);
    SYMF(partP, g_part);
#undef SYMF
#undef SYMH

    const long long BW = (long long)Bb*Ww;
    const float invs = 0.35355339059327373f;

    // ---- preamble (launch 5 = merged f0+ghn tgemm for ncu -s 5) -----------
    prep_all<<<(int)((P8/4 + 255)/256), 256>>>(W_mix, W_in, W_link, W_ih,
                                               W_hh, W_delta, pgain, b_ih, b_hh); // 0
    encode_kernel<<<Bb, 128>>>(x, embed);                                         // 1

    // 2: summary GEMM split-K x8  (3-term for h0 accuracy)
    {
        TG a = mkTG();
        a.Ahi = catH; a.Alo = catL; a.lda = 1536;
        a.Bhi = wmixH; a.Blo = wmixL; a.ldb = 1536;
        a.Cpart = partP; a.ldc = Ww; a.cBatch = BW;
        a.K = 1536; a.terms = 3; a.kSplit = 8;
        tgemm<<<dim3(4, 8, 8), 128, SMEM_DYN>>>(a);
    }
    sum_finalize<<<(Bb*Ww)/256, 256>>>(b_mix);                                    // 3

    // 4: pre[s] = summary @ W_in[s][:, W:]^T  (1-term)
    {
        TG a = mkTG();
        a.Ahi = hH; a.lda = Ww;
        a.Bhi = winH + Ww; a.ldb = 2*Ww; a.bBatch = (long long)Ww*2*Ww;
        a.Cf = preH; a.ldc = Ww; a.cBatch = BW;
        a.K = Ww;
        tgemm<<<dim3(4, 8, Ss), 128, SMEM_DYN>>>(a);
    }

    // merged: z<8 f0 = tanh(h@Win[:, :W]^T + pre + b_in);
    //         z>=8 ghn = hs@Whh_n^T + b_hh_n   (own geometry)
    auto launch_f0_ghn = [&]() {
        TG a = mkTG();
        a.Ahi = hH; a.lda = Ww; a.aBatch = 0;
        a.Bhi = winH; a.ldb = 2*Ww; a.bBatch = (long long)Ww*2*Ww;
        a.bias = b_in; a.biasBatch = Ww;
        a.DresH = preH; a.ldd = Ww; a.dBatch = BW;
        a.Cf = f0H; a.ldc = Ww; a.cBatch = BW;
        a.act = 1;
        a.A2hi = hsH; a.lda2 = Ww; a.aBatch2 = BW;
        a.B2hi = whhH + (long long)1024*Ww; a.ldb2 = Ww; a.bBatch2 = (long long)3*Ww*Ww;
        a.bias2 = b_hh + 1024; a.bias2Batch = 3*Ww;
        a.C2f = ghnH; a.ldc2 = Ww; a.cBatch2 = BW;
        a.act2 = 0; a.nx2 = 4;
        a.K = Ww;
        tgemm<<<dim3(4, 8, 16), 128, SMEM_DYN>>>(a);
    };
    launch_f0_ghn();                                                              // 5

    for (int t = 0; t < NSTEPS; ++t) {
        if (t > 0) launch_f0_ghn();
        // feats = tanh(f0 + roll(f0) @ W_link^T + b_link)
        {
            TG a = mkTG();
            a.Ahi = f0H; a.lda = Ww; a.aBatch = BW; a.aRot = 1;
            a.Bhi = wlkH; a.ldb = Ww; a.bBatch = (long long)Ww*Ww;
            a.bias = b_link; a.biasBatch = Ww;
            a.DresH = f0H; a.ldd = Ww; a.dBatch = BW;
            a.Cf = ftH; a.ldc = Ww; a.cBatch = BW;
            a.K = Ww; a.act = 1;
            tgemm<<<dim3(4, 8, Ss), 128, SMEM_DYN>>>(a);
        }
        // merged: z<8 rz = feats@Wih_rz^T + hs@Whh_rz^T + brz;
        //         z>=8 gin = feats@Wih_n^T + b_ih_n (x<4)
        {
            TG a = mkTG();
            a.Ahi = ftH; a.Alo = hsH; a.lda = Ww; a.aBatch = BW;
            a.Bhi = wihH; a.Blo = whhH; a.ldb = Ww; a.bBatch = (long long)3*Ww*Ww;
            a.bias = brzP; a.biasBatch = 1024;
            a.Cf = rzH; a.ldc = 1024; a.cBatch = (long long)Bb*1024;
            a.terms = 2; a.abPair = 1;
            a.A2hi = ftH; a.lda2 = Ww; a.aBatch2 = BW;
            a.B2hi = wihH + (long long)1024*Ww; a.ldb2 = Ww; a.bBatch2 = (long long)3*Ww*Ww;
            a.bias2 = b_ih + 1024; a.bias2Batch = 3*Ww;
            a.C2f = ginH; a.ldc2 = Ww; a.cBatch2 = BW;
            a.terms2 = 1; a.nx2 = 4;
            a.K = Ww;
            tgemm<<<dim3(8, 8, 16), 128, SMEM_DYN>>>(a);
        }
        gru_prism<<<dim3(Bb, Ss), 128>>>(W_gate, b_gate, phase);
        // upd = gate * tanh(f2 @ W_delta^T + b_delta) * invs
        {
            TG a = mkTG();
            a.Ahi = f2H; a.lda = Ww; a.aBatch = BW;
            a.Bhi = wdlH; a.ldb = Ww; a.bBatch = (long long)Ww*Ww;
            a.bias = b_delta; a.biasBatch = Ww;
            a.gate = gatep;
            a.Cf = updH; a.ldc = Ww; a.cBatch = BW;
            a.K = Ww; a.act = 1; a.scale = invs;
            tgemm<<<dim3(4, 8, Ss), 128, SMEM_DYN>>>(a);
        }
        if (t < NSTEPS - 1)
            h_update<<<(Bb*Ww)/512, 256>>>(decay);
        else
            h_final<<<Bb, 256>>>(decay, W_out, b_out, (float*)d_out);
    }
}